// round 1
// baseline (speedup 1.0000x reference)
#include <cuda_runtime.h>

#define HIDDEN 1024
#define HEADS  16
#define HDIM   64
#define RANK   16
#define SEQ    2048
#define BS     4
#define NTOK   (BS*SEQ)          /* 8192 */
#define QKVSZ  (NTOK*HIDDEN)     /* 8388608 floats per projection */

// Scratch (device globals: allocation-free per harness rules)
__device__ float g_weff[3*HIDDEN*HIDDEN];       // [p][n][k], 12 MB
__device__ float g_qkv[(size_t)3*QKVSZ];        // [p][(b*16+h)*2048+s][d], 100 MB

// ---------------------------------------------------------------------------
// Kernel 1: fold LoRA into effective weight: Weff = W + (1/16) * B @ A
// grid: (1024, 3), block: 256
// ---------------------------------------------------------------------------
__global__ void weff_kernel(const float* __restrict__ W,
                            const float* __restrict__ A,
                            const float* __restrict__ B,
                            int p) {
    int n = blockIdx.x;
    __shared__ float Brow[RANK];
    if (threadIdx.x < RANK)
        Brow[threadIdx.x] = B[n*RANK + threadIdx.x] * (1.0f/RANK);
    __syncthreads();
    float* dst = g_weff + (size_t)p*HIDDEN*HIDDEN + n*HIDDEN;
    const float* wr = W + (size_t)n*HIDDEN;
    for (int k = threadIdx.x; k < HIDDEN; k += blockDim.x) {
        float acc = wr[k];
        #pragma unroll
        for (int r = 0; r < RANK; r++)
            acc += Brow[r] * A[r*HIDDEN + k];
        dst[k] = acc;
    }
}

// ---------------------------------------------------------------------------
// Kernel 2: fused QKV projection GEMM.
// C[8192, 3072] = X[8192,1024] @ Weff^T, + bias, scattered into g_qkv with
// [b,h,s,d] layout for attention.
// 128x128 tile, BK=16, 256 threads, 8x8 per-thread microtile.
// grid: (24, 64)
// ---------------------------------------------------------------------------
__global__ __launch_bounds__(256) void qkv_gemm(
        const float* __restrict__ X,
        const float* __restrict__ bq,
        const float* __restrict__ bk,
        const float* __restrict__ bv) {
    __shared__ float As[16][128];
    __shared__ float Bsm[16][128];

    int tid = threadIdx.x;
    int bm = blockIdx.y * 128;
    int bn = blockIdx.x * 128;
    int tx = tid & 15;
    int ty = tid >> 4;

    float acc[8][8];
    #pragma unroll
    for (int i = 0; i < 8; i++)
        #pragma unroll
        for (int j = 0; j < 8; j++) acc[i][j] = 0.0f;

    const float* Wp = g_weff;  // [3072][1024]

    for (int k0 = 0; k0 < HIDDEN; k0 += 16) {
        #pragma unroll
        for (int it = 0; it < 2; it++) {
            int vid = tid + it*256;        // 0..511 float4 slots
            int row = vid >> 2;            // 0..127
            int kk  = (vid & 3) << 2;      // 0,4,8,12
            float4 xa = *(const float4*)&X[(size_t)(bm+row)*HIDDEN + k0 + kk];
            As[kk+0][row] = xa.x; As[kk+1][row] = xa.y;
            As[kk+2][row] = xa.z; As[kk+3][row] = xa.w;
            float4 wb = *(const float4*)&Wp[(size_t)(bn+row)*HIDDEN + k0 + kk];
            Bsm[kk+0][row] = wb.x; Bsm[kk+1][row] = wb.y;
            Bsm[kk+2][row] = wb.z; Bsm[kk+3][row] = wb.w;
        }
        __syncthreads();

        #pragma unroll
        for (int kk = 0; kk < 16; kk++) {
            float4 a0 = *(const float4*)&As[kk][ty*8];
            float4 a1 = *(const float4*)&As[kk][ty*8 + 4];
            float4 b0 = *(const float4*)&Bsm[kk][tx*8];
            float4 b1 = *(const float4*)&Bsm[kk][tx*8 + 4];
            float a[8] = {a0.x,a0.y,a0.z,a0.w, a1.x,a1.y,a1.z,a1.w};
            float b[8] = {b0.x,b0.y,b0.z,b0.w, b1.x,b1.y,b1.z,b1.w};
            #pragma unroll
            for (int i = 0; i < 8; i++)
                #pragma unroll
                for (int j = 0; j < 8; j++)
                    acc[i][j] += a[i] * b[j];
        }
        __syncthreads();
    }

    int p    = bn >> 10;       // projection 0/1/2 (tile never crosses: 1024%128==0)
    int coff = bn & 1023;
    const float* bias = (p == 0) ? bq : ((p == 1) ? bk : bv);

    #pragma unroll
    for (int i = 0; i < 8; i++) {
        int m  = bm + ty*8 + i;
        int bb = m >> 11;        // batch
        int s  = m & 2047;       // seq pos
        #pragma unroll
        for (int j = 0; j < 8; j++) {
            int col = coff + tx*8 + j;
            int h = col >> 6;
            int d = col & 63;
            g_qkv[(size_t)p*QKVSZ + ((size_t)(bb*HEADS + h)*SEQ + s)*HDIM + d]
                = acc[i][j] + bias[col];
        }
    }
}

// ---------------------------------------------------------------------------
// Kernel 3: flash attention, fp32. One CTA = one (b,h), 64 query rows.
// 64-key chunks, online softmax, P·V via warp shuffles (no P in smem).
// block: 128 threads (ty=tid/8 -> 4 q-rows each; tx=tid%8 -> 8 cols each)
// grid: (32, 64)
// ---------------------------------------------------------------------------
#define QSTR 65   // Qs[q][d], scalar access, conflict-free
#define KSTR 68   // Kt[d][k], float4-aligned stride
#define VSTR 68   // Vs[k][d], float4-aligned stride
#define ATTN_SMEM ((64*QSTR + 64*KSTR + 64*VSTR) * 4)

__global__ __launch_bounds__(128) void attn_kernel(
        const float* __restrict__ mask,
        float* __restrict__ out) {
    extern __shared__ float sm[];
    float* Qs = sm;                 // [64][QSTR]
    float* Kt = sm + 64*QSTR;       // [64][KSTR]  Kt[d][k]
    float* Vs = Kt + 64*KSTR;       // [64][VSTR]  Vs[k][d]

    int tid = threadIdx.x;
    int tx = tid & 7;
    int ty = tid >> 3;
    int lane = tid & 31;
    int bh = blockIdx.y;
    int b  = bh >> 4;
    int h  = bh & 15;
    int q0 = blockIdx.x * 64;

    const float* Qg = g_qkv + (size_t)bh*SEQ*HDIM + (size_t)q0*HDIM;
    const float* Kg = g_qkv + (size_t)QKVSZ   + (size_t)bh*SEQ*HDIM;
    const float* Vg = g_qkv + (size_t)2*QKVSZ + (size_t)bh*SEQ*HDIM;
    const float* mrow = mask + b*SEQ;

    // Load Q tile (64x64): 1024 float4, 8 per thread
    #pragma unroll
    for (int it = 0; it < 8; it++) {
        int vid = tid + it*128;
        int row = vid >> 4;
        int d0  = (vid & 15) << 2;
        float4 v = *(const float4*)&Qg[row*HDIM + d0];
        Qs[row*QSTR + d0+0] = v.x; Qs[row*QSTR + d0+1] = v.y;
        Qs[row*QSTR + d0+2] = v.z; Qs[row*QSTR + d0+3] = v.w;
    }

    float o[4][8];
    #pragma unroll
    for (int i = 0; i < 4; i++)
        #pragma unroll
        for (int j = 0; j < 8; j++) o[i][j] = 0.0f;
    float mrun[4], lrun[4];
    #pragma unroll
    for (int i = 0; i < 4; i++) { mrun[i] = -1e30f; lrun[i] = 0.0f; }

    float s[4][8];

    for (int kc = 0; kc < SEQ; kc += 64) {
        // Load K chunk (transposed into Kt[d][k]) and V chunk (Vs[k][d])
        #pragma unroll
        for (int it = 0; it < 8; it++) {
            int vid = tid + it*128;
            int row = vid >> 4;
            int d0  = (vid & 15) << 2;
            float4 kv = *(const float4*)&Kg[(size_t)(kc+row)*HDIM + d0];
            Kt[(d0+0)*KSTR + row] = kv.x; Kt[(d0+1)*KSTR + row] = kv.y;
            Kt[(d0+2)*KSTR + row] = kv.z; Kt[(d0+3)*KSTR + row] = kv.w;
            float4 vv = *(const float4*)&Vg[(size_t)(kc+row)*HDIM + d0];
            *(float4*)&Vs[row*VSTR + d0] = vv;
        }
        __syncthreads();

        // S = Q K^T for this chunk
        #pragma unroll
        for (int i = 0; i < 4; i++)
            #pragma unroll
            for (int j = 0; j < 8; j++) s[i][j] = 0.0f;

        for (int d = 0; d < 64; d++) {
            float a[4];
            #pragma unroll
            for (int i = 0; i < 4; i++) a[i] = Qs[(ty*4+i)*QSTR + d];
            float4 b0 = *(const float4*)&Kt[d*KSTR + tx*8];
            float4 b1 = *(const float4*)&Kt[d*KSTR + tx*8 + 4];
            float bb[8] = {b0.x,b0.y,b0.z,b0.w, b1.x,b1.y,b1.z,b1.w};
            #pragma unroll
            for (int i = 0; i < 4; i++)
                #pragma unroll
                for (int j = 0; j < 8; j++)
                    s[i][j] += a[i] * bb[j];
        }

        // scale + mask + online softmax update
        float mk[8];
        #pragma unroll
        for (int j = 0; j < 8; j++) mk[j] = mrow[kc + tx*8 + j];

        #pragma unroll
        for (int i = 0; i < 4; i++) {
            #pragma unroll
            for (int j = 0; j < 8; j++) s[i][j] = s[i][j]*0.125f + mk[j];
            float mx = s[i][0];
            #pragma unroll
            for (int j = 1; j < 8; j++) mx = fmaxf(mx, s[i][j]);
            mx = fmaxf(mx, __shfl_xor_sync(0xffffffffu, mx, 1));
            mx = fmaxf(mx, __shfl_xor_sync(0xffffffffu, mx, 2));
            mx = fmaxf(mx, __shfl_xor_sync(0xffffffffu, mx, 4));
            float mnew = fmaxf(mrun[i], mx);
            float corr = __expf(mrun[i] - mnew);
            float ls = 0.0f;
            #pragma unroll
            for (int j = 0; j < 8; j++) {
                float p = __expf(s[i][j] - mnew);
                s[i][j] = p;
                ls += p;
            }
            ls += __shfl_xor_sync(0xffffffffu, ls, 1);
            ls += __shfl_xor_sync(0xffffffffu, ls, 2);
            ls += __shfl_xor_sync(0xffffffffu, ls, 4);
            lrun[i] = lrun[i]*corr + ls;
            mrun[i] = mnew;
            #pragma unroll
            for (int j = 0; j < 8; j++) o[i][j] *= corr;
        }

        // O += P @ V  (P distributed in registers; broadcast via shuffle)
        int base = lane & 24;
        #pragma unroll
        for (int k = 0; k < 64; k++) {
            int src = base | (k >> 3);
            float p0 = __shfl_sync(0xffffffffu, s[0][k & 7], src);
            float p1 = __shfl_sync(0xffffffffu, s[1][k & 7], src);
            float p2 = __shfl_sync(0xffffffffu, s[2][k & 7], src);
            float p3 = __shfl_sync(0xffffffffu, s[3][k & 7], src);
            float4 v0 = *(const float4*)&Vs[k*VSTR + tx*8];
            float4 v1 = *(const float4*)&Vs[k*VSTR + tx*8 + 4];
            float vv[8] = {v0.x,v0.y,v0.z,v0.w, v1.x,v1.y,v1.z,v1.w};
            #pragma unroll
            for (int j = 0; j < 8; j++) {
                o[0][j] += p0 * vv[j];
                o[1][j] += p1 * vv[j];
                o[2][j] += p2 * vv[j];
                o[3][j] += p3 * vv[j];
            }
        }
        __syncthreads();
    }

    // epilogue: normalize and write out[b][q][h*64+d]
    #pragma unroll
    for (int i = 0; i < 4; i++) {
        float inv = 1.0f / lrun[i];
        int q = q0 + ty*4 + i;
        float* orow = out + ((size_t)b*SEQ + q)*HIDDEN + h*HDIM + tx*8;
        float4 w0, w1;
        w0.x = o[i][0]*inv; w0.y = o[i][1]*inv; w0.z = o[i][2]*inv; w0.w = o[i][3]*inv;
        w1.x = o[i][4]*inv; w1.y = o[i][5]*inv; w1.z = o[i][6]*inv; w1.w = o[i][7]*inv;
        *(float4*)&orow[0] = w0;
        *(float4*)&orow[4] = w1;
    }
}

// ---------------------------------------------------------------------------
extern "C" void kernel_launch(void* const* d_in, const int* in_sizes, int n_in,
                              void* d_out, int out_size) {
    const float* hs   = (const float*)d_in[0];
    const float* mask = (const float*)d_in[1];
    const float* Wq = (const float*)d_in[2];
    const float* bq = (const float*)d_in[3];
    const float* Aq = (const float*)d_in[4];
    const float* Bq = (const float*)d_in[5];
    const float* Wk = (const float*)d_in[6];
    const float* bk = (const float*)d_in[7];
    const float* Ak = (const float*)d_in[8];
    const float* Bk = (const float*)d_in[9];
    const float* Wv = (const float*)d_in[10];
    const float* bv = (const float*)d_in[11];
    const float* Av = (const float*)d_in[12];
    const float* Bv = (const float*)d_in[13];
    float* out = (float*)d_out;

    // 1. Fold LoRA into effective weights
    weff_kernel<<<HIDDEN, 256>>>(Wq, Aq, Bq, 0);
    weff_kernel<<<HIDDEN, 256>>>(Wk, Ak, Bk, 1);
    weff_kernel<<<HIDDEN, 256>>>(Wv, Av, Bv, 2);

    // 2. Fused QKV GEMM
    {
        dim3 grid(3*HIDDEN/128, NTOK/128);
        qkv_gemm<<<grid, 256>>>(hs, bq, bk, bv);
    }

    // 3. Flash attention
    {
        static int smem_set = 0;
        if (!smem_set) {
            cudaFuncSetAttribute(attn_kernel,
                cudaFuncAttributeMaxDynamicSharedMemorySize, ATTN_SMEM);
            smem_set = 1;
        }
        dim3 grid(SEQ/64, BS*HEADS);
        attn_kernel<<<grid, 128, ATTN_SMEM>>>(mask, out);
    }
}

// round 2
// speedup vs baseline: 1.0670x; 1.0670x over previous
#include <cuda_runtime.h>

#define HIDDEN 1024
#define HEADS  16
#define HDIM   64
#define RANK   16
#define SEQ    2048
#define BS     4
#define NTOK   (BS*SEQ)          /* 8192 */
#define QKVSZ  (NTOK*HIDDEN)     /* 8388608 floats per projection */

typedef unsigned long long u64;

// ---- packed f32x2 helpers (sm_103a) ---------------------------------------
__device__ __forceinline__ u64 pk2(float x, float y) {
    u64 r; asm("mov.b64 %0,{%1,%2};" : "=l"(r) : "f"(x), "f"(y)); return r;
}
__device__ __forceinline__ u64 dup2(float x) { return pk2(x, x); }
__device__ __forceinline__ void unpk2(u64 v, float& x, float& y) {
    asm("mov.b64 {%0,%1},%2;" : "=f"(x), "=f"(y) : "l"(v));
}
__device__ __forceinline__ void fma2(u64& d, u64 a, u64 b) {
    asm("fma.rn.f32x2 %0,%1,%2,%0;" : "+l"(d) : "l"(a), "l"(b));
}
__device__ __forceinline__ void mul2(u64& d, u64 a) {
    asm("mul.rn.f32x2 %0,%0,%1;" : "+l"(d) : "l"(a));
}

// Scratch (device globals: allocation-free per harness rules)
__device__ float g_weff[3*HIDDEN*HIDDEN];       // [p][n][k], 12 MB
__device__ float g_qkv[(size_t)3*QKVSZ];        // [p][(b*16+h)*2048+s][d], 100 MB

// ---------------------------------------------------------------------------
// Kernel 1: fold LoRA into effective weight: Weff = W + (1/16) * B @ A
// ---------------------------------------------------------------------------
__global__ void weff_kernel(const float* __restrict__ W,
                            const float* __restrict__ A,
                            const float* __restrict__ B,
                            int p) {
    int n = blockIdx.x;
    __shared__ float Brow[RANK];
    if (threadIdx.x < RANK)
        Brow[threadIdx.x] = B[n*RANK + threadIdx.x] * (1.0f/RANK);
    __syncthreads();
    float* dst = g_weff + (size_t)p*HIDDEN*HIDDEN + n*HIDDEN;
    const float* wr = W + (size_t)n*HIDDEN;
    for (int k = threadIdx.x; k < HIDDEN; k += blockDim.x) {
        float acc = wr[k];
        #pragma unroll
        for (int r = 0; r < RANK; r++)
            acc += Brow[r] * A[r*HIDDEN + k];
        dst[k] = acc;
    }
}

// ---------------------------------------------------------------------------
// Kernel 2: fused QKV projection GEMM (FFMA2 inner loop).
// C[8192, 3072] = X[8192,1024] @ Weff^T, + bias, scattered into g_qkv.
// 128x128 tile, BK=16, 256 threads, 8x8 microtile packed as 8x(4 f32x2).
// ---------------------------------------------------------------------------
__global__ __launch_bounds__(256) void qkv_gemm(
        const float* __restrict__ X,
        const float* __restrict__ bq,
        const float* __restrict__ bk,
        const float* __restrict__ bv) {
    __shared__ float As[16][128];
    __shared__ float Bsm[16][128];

    int tid = threadIdx.x;
    int bm = blockIdx.y * 128;
    int bn = blockIdx.x * 128;
    int tx = tid & 15;
    int ty = tid >> 4;

    u64 acc2[8][4];
    #pragma unroll
    for (int i = 0; i < 8; i++)
        #pragma unroll
        for (int j = 0; j < 4; j++) acc2[i][j] = 0ull;

    const float* Wp = g_weff;  // [3072][1024]

    for (int k0 = 0; k0 < HIDDEN; k0 += 16) {
        #pragma unroll
        for (int it = 0; it < 2; it++) {
            int vid = tid + it*256;        // 0..511 float4 slots
            int row = vid >> 2;            // 0..127
            int kk  = (vid & 3) << 2;      // 0,4,8,12
            float4 xa = *(const float4*)&X[(size_t)(bm+row)*HIDDEN + k0 + kk];
            As[kk+0][row] = xa.x; As[kk+1][row] = xa.y;
            As[kk+2][row] = xa.z; As[kk+3][row] = xa.w;
            float4 wb = *(const float4*)&Wp[(size_t)(bn+row)*HIDDEN + k0 + kk];
            Bsm[kk+0][row] = wb.x; Bsm[kk+1][row] = wb.y;
            Bsm[kk+2][row] = wb.z; Bsm[kk+3][row] = wb.w;
        }
        __syncthreads();

        #pragma unroll
        for (int kk = 0; kk < 16; kk++) {
            float4 a0 = *(const float4*)&As[kk][ty*8];
            float4 a1 = *(const float4*)&As[kk][ty*8 + 4];
            float a[8] = {a0.x,a0.y,a0.z,a0.w, a1.x,a1.y,a1.z,a1.w};
            ulonglong2 bv0 = *(const ulonglong2*)&Bsm[kk][tx*8];
            ulonglong2 bv1 = *(const ulonglong2*)&Bsm[kk][tx*8 + 4];
            u64 b2[4] = {bv0.x, bv0.y, bv1.x, bv1.y};
            #pragma unroll
            for (int i = 0; i < 8; i++) {
                u64 ai = dup2(a[i]);
                #pragma unroll
                for (int j = 0; j < 4; j++)
                    fma2(acc2[i][j], ai, b2[j]);
            }
        }
        __syncthreads();
    }

    int p    = bn >> 10;       // projection 0/1/2 (tile never crosses: 1024%128==0)
    int coff = bn & 1023;
    const float* bias = (p == 0) ? bq : ((p == 1) ? bk : bv);

    int colb = coff + tx*8;
    float4 bia0 = *(const float4*)&bias[colb];
    float4 bia1 = *(const float4*)&bias[colb + 4];

    #pragma unroll
    for (int i = 0; i < 8; i++) {
        int m  = bm + ty*8 + i;
        int bb = m >> 11;        // batch
        int s  = m & 2047;       // seq pos
        float af[8];
        #pragma unroll
        for (int j = 0; j < 4; j++) unpk2(acc2[i][j], af[2*j], af[2*j+1]);
        // 8 consecutive cols never cross a 64-boundary (colb % 8 == 0, coff%128==0)
        int h = colb >> 6;
        int d = colb & 63;
        float* dst = &g_qkv[(size_t)p*QKVSZ + ((size_t)(bb*HEADS + h)*SEQ + s)*HDIM + d];
        float4 w0, w1;
        w0.x = af[0]+bia0.x; w0.y = af[1]+bia0.y; w0.z = af[2]+bia0.z; w0.w = af[3]+bia0.w;
        w1.x = af[4]+bia1.x; w1.y = af[5]+bia1.y; w1.z = af[6]+bia1.z; w1.w = af[7]+bia1.w;
        *(float4*)&dst[0] = w0;
        *(float4*)&dst[4] = w1;
    }
}

// ---------------------------------------------------------------------------
// Kernel 3: flash attention, fp32 + FFMA2. One CTA = one (b,h), 64 q rows.
// 64-key chunks, online softmax, P staged through smem (no shuffles in PV).
// block: 128 threads (ty=tid/8 -> 4 q-rows each; tx=tid%8 -> 8 cols each)
// ---------------------------------------------------------------------------
#define QSTR 65   // Qs[q][d]
#define KSTR 68   // Kt[d][k], 16B-aligned stride
#define VSTR 68   // Vs[k][d]
#define PSTR 68   // Ps[q][k]
#define ATTN_SMEM ((64*QSTR + 64*KSTR + 64*VSTR + 64*PSTR) * 4)

__global__ __launch_bounds__(128) void attn_kernel(
        const float* __restrict__ mask,
        float* __restrict__ out) {
    extern __shared__ float sm[];
    float* Qs = sm;                 // [64][QSTR]
    float* Kt = sm + 64*QSTR;       // [64][KSTR]  Kt[d][k]
    float* Vs = Kt + 64*KSTR;       // [64][VSTR]  Vs[k][d]
    float* Ps = Vs + 64*VSTR;       // [64][PSTR]  Ps[q][k]

    int tid = threadIdx.x;
    int tx = tid & 7;
    int ty = tid >> 3;
    int bh = blockIdx.y;
    int b  = bh >> 4;
    int h  = bh & 15;
    int q0 = blockIdx.x * 64;

    const float* Qg = g_qkv + (size_t)bh*SEQ*HDIM + (size_t)q0*HDIM;
    const float* Kg = g_qkv + (size_t)QKVSZ   + (size_t)bh*SEQ*HDIM;
    const float* Vg = g_qkv + (size_t)2*QKVSZ + (size_t)bh*SEQ*HDIM;
    const float* mrow = mask + b*SEQ;

    // Load Q tile (64x64)
    #pragma unroll
    for (int it = 0; it < 8; it++) {
        int vid = tid + it*128;
        int row = vid >> 4;
        int d0  = (vid & 15) << 2;
        float4 v = *(const float4*)&Qg[row*HDIM + d0];
        Qs[row*QSTR + d0+0] = v.x; Qs[row*QSTR + d0+1] = v.y;
        Qs[row*QSTR + d0+2] = v.z; Qs[row*QSTR + d0+3] = v.w;
    }

    u64 o2[4][4];
    #pragma unroll
    for (int i = 0; i < 4; i++)
        #pragma unroll
        for (int j = 0; j < 4; j++) o2[i][j] = 0ull;
    float mrun[4], lrun[4];
    #pragma unroll
    for (int i = 0; i < 4; i++) { mrun[i] = -1e30f; lrun[i] = 0.0f; }

    for (int kc = 0; kc < SEQ; kc += 64) {
        // Load K chunk transposed (Kt[d][k]) and V chunk (Vs[k][d])
        #pragma unroll
        for (int it = 0; it < 8; it++) {
            int vid = tid + it*128;
            int row = vid >> 4;
            int d0  = (vid & 15) << 2;
            float4 kv = *(const float4*)&Kg[(size_t)(kc+row)*HDIM + d0];
            Kt[(d0+0)*KSTR + row] = kv.x; Kt[(d0+1)*KSTR + row] = kv.y;
            Kt[(d0+2)*KSTR + row] = kv.z; Kt[(d0+3)*KSTR + row] = kv.w;
            float4 vv = *(const float4*)&Vg[(size_t)(kc+row)*HDIM + d0];
            *(float4*)&Vs[row*VSTR + d0] = vv;
        }
        __syncthreads();

        // S = Q K^T for this chunk (FFMA2)
        u64 s2[4][4];
        #pragma unroll
        for (int i = 0; i < 4; i++)
            #pragma unroll
            for (int j = 0; j < 4; j++) s2[i][j] = 0ull;

        for (int d = 0; d < 64; d++) {
            float a[4];
            #pragma unroll
            for (int i = 0; i < 4; i++) a[i] = Qs[(ty*4+i)*QSTR + d];
            ulonglong2 kv0 = *(const ulonglong2*)&Kt[d*KSTR + tx*8];
            ulonglong2 kv1 = *(const ulonglong2*)&Kt[d*KSTR + tx*8 + 4];
            u64 b2[4] = {kv0.x, kv0.y, kv1.x, kv1.y};
            #pragma unroll
            for (int i = 0; i < 4; i++) {
                u64 ai = dup2(a[i]);
                #pragma unroll
                for (int j = 0; j < 4; j++)
                    fma2(s2[i][j], ai, b2[j]);
            }
        }

        // scale + mask + online softmax
        float s[4][8];
        #pragma unroll
        for (int i = 0; i < 4; i++)
            #pragma unroll
            for (int j = 0; j < 4; j++) unpk2(s2[i][j], s[i][2*j], s[i][2*j+1]);

        float mk[8];
        #pragma unroll
        for (int j = 0; j < 8; j++) mk[j] = mrow[kc + tx*8 + j];

        #pragma unroll
        for (int i = 0; i < 4; i++) {
            #pragma unroll
            for (int j = 0; j < 8; j++) s[i][j] = s[i][j]*0.125f + mk[j];
            float mx = s[i][0];
            #pragma unroll
            for (int j = 1; j < 8; j++) mx = fmaxf(mx, s[i][j]);
            mx = fmaxf(mx, __shfl_xor_sync(0xffffffffu, mx, 1));
            mx = fmaxf(mx, __shfl_xor_sync(0xffffffffu, mx, 2));
            mx = fmaxf(mx, __shfl_xor_sync(0xffffffffu, mx, 4));
            float mnew = fmaxf(mrun[i], mx);
            float corr = __expf(mrun[i] - mnew);
            float ls = 0.0f;
            #pragma unroll
            for (int j = 0; j < 8; j++) {
                float p = __expf(s[i][j] - mnew);
                s[i][j] = p;
                ls += p;
            }
            ls += __shfl_xor_sync(0xffffffffu, ls, 1);
            ls += __shfl_xor_sync(0xffffffffu, ls, 2);
            ls += __shfl_xor_sync(0xffffffffu, ls, 4);
            lrun[i] = lrun[i]*corr + ls;
            mrun[i] = mnew;
            u64 c2 = dup2(corr);
            #pragma unroll
            for (int j = 0; j < 4; j++) mul2(o2[i][j], c2);
            // stage P into smem
            float4 p0, p1;
            p0.x = s[i][0]; p0.y = s[i][1]; p0.z = s[i][2]; p0.w = s[i][3];
            p1.x = s[i][4]; p1.y = s[i][5]; p1.z = s[i][6]; p1.w = s[i][7];
            *(float4*)&Ps[(ty*4+i)*PSTR + tx*8]     = p0;
            *(float4*)&Ps[(ty*4+i)*PSTR + tx*8 + 4] = p1;
        }
        __syncthreads();

        // O += P @ V  (FFMA2, P from smem)
        for (int k = 0; k < 64; k++) {
            float p[4];
            #pragma unroll
            for (int i = 0; i < 4; i++) p[i] = Ps[(ty*4+i)*PSTR + k];
            ulonglong2 v0 = *(const ulonglong2*)&Vs[k*VSTR + tx*8];
            ulonglong2 v1 = *(const ulonglong2*)&Vs[k*VSTR + tx*8 + 4];
            u64 v2[4] = {v0.x, v0.y, v1.x, v1.y};
            #pragma unroll
            for (int i = 0; i < 4; i++) {
                u64 pi = dup2(p[i]);
                #pragma unroll
                for (int j = 0; j < 4; j++)
                    fma2(o2[i][j], pi, v2[j]);
            }
        }
        __syncthreads();
    }

    // epilogue: normalize and write out[b][q][h*64+d]
    #pragma unroll
    for (int i = 0; i < 4; i++) {
        float inv = 1.0f / lrun[i];
        float of[8];
        #pragma unroll
        for (int j = 0; j < 4; j++) unpk2(o2[i][j], of[2*j], of[2*j+1]);
        int q = q0 + ty*4 + i;
        float* orow = out + ((size_t)b*SEQ + q)*HIDDEN + h*HDIM + tx*8;
        float4 w0, w1;
        w0.x = of[0]*inv; w0.y = of[1]*inv; w0.z = of[2]*inv; w0.w = of[3]*inv;
        w1.x = of[4]*inv; w1.y = of[5]*inv; w1.z = of[6]*inv; w1.w = of[7]*inv;
        *(float4*)&orow[0] = w0;
        *(float4*)&orow[4] = w1;
    }
}

// ---------------------------------------------------------------------------
extern "C" void kernel_launch(void* const* d_in, const int* in_sizes, int n_in,
                              void* d_out, int out_size) {
    const float* hs   = (const float*)d_in[0];
    const float* mask = (const float*)d_in[1];
    const float* Wq = (const float*)d_in[2];
    const float* bq = (const float*)d_in[3];
    const float* Aq = (const float*)d_in[4];
    const float* Bq = (const float*)d_in[5];
    const float* Wk = (const float*)d_in[6];
    const float* bk = (const float*)d_in[7];
    const float* Ak = (const float*)d_in[8];
    const float* Bk = (const float*)d_in[9];
    const float* Wv = (const float*)d_in[10];
    const float* bv = (const float*)d_in[11];
    const float* Av = (const float*)d_in[12];
    const float* Bv = (const float*)d_in[13];
    float* out = (float*)d_out;

    // 1. Fold LoRA into effective weights
    weff_kernel<<<HIDDEN, 256>>>(Wq, Aq, Bq, 0);
    weff_kernel<<<HIDDEN, 256>>>(Wk, Ak, Bk, 1);
    weff_kernel<<<HIDDEN, 256>>>(Wv, Av, Bv, 2);

    // 2. Fused QKV GEMM
    {
        dim3 grid(3*HIDDEN/128, NTOK/128);
        qkv_gemm<<<grid, 256>>>(hs, bq, bk, bv);
    }

    // 3. Flash attention
    {
        static int smem_set = 0;
        if (!smem_set) {
            cudaFuncSetAttribute(attn_kernel,
                cudaFuncAttributeMaxDynamicSharedMemorySize, ATTN_SMEM);
            smem_set = 1;
        }
        dim3 grid(SEQ/64, BS*HEADS);
        attn_kernel<<<grid, 128, ATTN_SMEM>>>(mask, out);
    }
}

// round 5
// speedup vs baseline: 4.2957x; 4.0259x over previous
#include <cuda_runtime.h>
#include <cuda_bf16.h>
#include <cstdint>

#define HIDDEN 1024
#define HEADS  16
#define HDIM   64
#define RANK   16
#define SEQ    2048
#define BS     4
#define NTOK   (BS*SEQ)          /* 8192 */
#define NBH    (BS*HEADS)        /* 64 */

// ---------------- scratch (device globals; no allocation) -------------------
__device__ __align__(16) __nv_bfloat16 g_xh[(size_t)NTOK*HIDDEN];
__device__ __align__(16) __nv_bfloat16 g_xl[(size_t)NTOK*HIDDEN];
__device__ __align__(16) __nv_bfloat16 g_wh[(size_t)3*HIDDEN*HIDDEN];
__device__ __align__(16) __nv_bfloat16 g_wl[(size_t)3*HIDDEN*HIDDEN];
// Q(K,V) in [bh][seq][64] layout, bf16 hi/lo (Q pre-scaled by 0.125)
__device__ __align__(16) __nv_bfloat16 gQh[(size_t)NBH*SEQ*HDIM];
__device__ __align__(16) __nv_bfloat16 gQl[(size_t)NBH*SEQ*HDIM];
__device__ __align__(16) __nv_bfloat16 gKh[(size_t)NBH*SEQ*HDIM];
__device__ __align__(16) __nv_bfloat16 gKl[(size_t)NBH*SEQ*HDIM];
__device__ __align__(16) __nv_bfloat16 gVh[(size_t)NBH*SEQ*HDIM];
__device__ __align__(16) __nv_bfloat16 gVl[(size_t)NBH*SEQ*HDIM];

// ---------------- low-level helpers ----------------------------------------
__device__ __forceinline__ uint32_t smem_u32(const void* p) {
    uint32_t a;
    asm("{ .reg .u64 t; cvta.to.shared.u64 t, %1; cvt.u32.u64 %0, t; }"
        : "=r"(a) : "l"(p));
    return a;
}
__device__ __forceinline__ void cpa16(uint32_t dst, const void* src) {
    asm volatile("cp.async.cg.shared.global [%0],[%1],16;"
                 :: "r"(dst), "l"(__cvta_generic_to_global(src)));
}
#define CP_COMMIT() asm volatile("cp.async.commit_group;" ::: "memory")
#define CP_WAIT(n)  asm volatile("cp.async.wait_group %0;" :: "n"(n) : "memory")

#define SWZ(o) ((o) ^ (((o) >> 3) & 0x70))

__device__ __forceinline__ void ldsm4(uint32_t r[4], uint32_t a) {
    asm volatile("ldmatrix.sync.aligned.m8n8.x4.shared.b16 {%0,%1,%2,%3},[%4];"
        : "=r"(r[0]), "=r"(r[1]), "=r"(r[2]), "=r"(r[3]) : "r"(a));
}
__device__ __forceinline__ void ldsm4t(uint32_t r[4], uint32_t a) {
    asm volatile("ldmatrix.sync.aligned.m8n8.x4.trans.shared.b16 {%0,%1,%2,%3},[%4];"
        : "=r"(r[0]), "=r"(r[1]), "=r"(r[2]), "=r"(r[3]) : "r"(a));
}
__device__ __forceinline__ void mma16816(float c[4], const uint32_t a[4],
                                         uint32_t b0, uint32_t b1) {
    asm volatile(
        "mma.sync.aligned.m16n8k16.row.col.f32.bf16.bf16.f32 "
        "{%0,%1,%2,%3},{%4,%5,%6,%7},{%8,%9},{%0,%1,%2,%3};"
        : "+f"(c[0]), "+f"(c[1]), "+f"(c[2]), "+f"(c[3])
        : "r"(a[0]), "r"(a[1]), "r"(a[2]), "r"(a[3]), "r"(b0), "r"(b1));
}
// pack two f32 -> bf16x2 {lo=x, hi=y}
__device__ __forceinline__ uint32_t pkbf(float x, float y) {
    uint32_t r;
    asm("cvt.rn.bf16x2.f32 %0,%1,%2;" : "=r"(r) : "f"(y), "f"(x));
    return r;
}
__device__ __forceinline__ float bflo(uint32_t p) { return __uint_as_float(p << 16); }
__device__ __forceinline__ float bfhi(uint32_t p) { return __uint_as_float(p & 0xFFFF0000u); }

// ---------------------------------------------------------------------------
// Kernel 1a: split X into bf16 hi/lo.
// ---------------------------------------------------------------------------
__global__ void xsplit_kernel(const float* __restrict__ X) {
    size_t i = ((size_t)blockIdx.x * 256 + threadIdx.x) * 4;
    float4 v = *(const float4*)&X[i];
    uint32_t h01 = pkbf(v.x, v.y), h23 = pkbf(v.z, v.w);
    uint32_t l01 = pkbf(v.x - bflo(h01), v.y - bfhi(h01));
    uint32_t l23 = pkbf(v.z - bflo(h23), v.w - bfhi(h23));
    *(uint2*)&g_xh[i] = make_uint2(h01, h23);
    *(uint2*)&g_xl[i] = make_uint2(l01, l23);
}

// ---------------------------------------------------------------------------
// Kernel 1b: Weff = W + (1/16) B @ A, split into bf16 hi/lo.
// ---------------------------------------------------------------------------
__global__ void wsplit_kernel(const float* __restrict__ W,
                              const float* __restrict__ A,
                              const float* __restrict__ B,
                              int p) {
    int n = blockIdx.x;
    __shared__ float Brow[RANK];
    if (threadIdx.x < RANK)
        Brow[threadIdx.x] = B[n*RANK + threadIdx.x] * (1.0f/RANK);
    __syncthreads();
    size_t roff = ((size_t)p*HIDDEN + n) * HIDDEN;
    const float* wr = W + (size_t)n*HIDDEN;
    for (int k = threadIdx.x; k < HIDDEN; k += blockDim.x) {
        float acc = wr[k];
        #pragma unroll
        for (int r = 0; r < RANK; r++)
            acc += Brow[r] * A[r*HIDDEN + k];
        uint32_t h = pkbf(acc, 0.0f);
        g_wh[roff + k] = __ushort_as_bfloat16((unsigned short)(h & 0xFFFF));
        float l = acc - bflo(h);
        uint32_t lp = pkbf(l, 0.0f);
        g_wl[roff + k] = __ushort_as_bfloat16((unsigned short)(lp & 0xFFFF));
    }
}

// ---------------------------------------------------------------------------
// Kernel 2: QKV GEMM on mma.sync bf16 split (3-term).
// ---------------------------------------------------------------------------
#define GTILE 16384                  /* 128x64 bf16, 128B rows, swizzled */
#define GSTAGE (4*GTILE)             /* Xh,Xl,Wh,Wl */
#define GEMM_SMEM (2*GSTAGE)         /* 131072 */

__global__ __launch_bounds__(256) void qkv_gemm_mma(
        const float* __restrict__ bq,
        const float* __restrict__ bk,
        const float* __restrict__ bv) {
    extern __shared__ char smg[];
    uint32_t sb = smem_u32(smg);
    int tid = threadIdx.x, lane = tid & 31, wid = tid >> 5;
    int bm = blockIdx.y * 128, bn = blockIdx.x * 128;
    int wm = (wid >> 2) * 64, wn = (wid & 3) * 32;

    float acc[4][4][4];
    #pragma unroll
    for (int a = 0; a < 4; a++)
        #pragma unroll
        for (int b = 0; b < 4; b++)
            #pragma unroll
            for (int c = 0; c < 4; c++) acc[a][b][c] = 0.0f;

    auto load_stage = [&](int s, int c) {
        int k0 = c * 64;
        uint32_t base = sb + s * GSTAGE;
        #pragma unroll
        for (int it = 0; it < 4; it++) {
            int idx = tid + it*256;
            int r = idx >> 3, cb = (idx & 7) << 4;
            uint32_t so = SWZ(r*128 + cb);
            const char* xh = (const char*)(g_xh + (size_t)(bm + r)*HIDDEN + k0) + cb;
            const char* xl = (const char*)(g_xl + (size_t)(bm + r)*HIDDEN + k0) + cb;
            const char* wh = (const char*)(g_wh + (size_t)(bn + r)*HIDDEN + k0) + cb;
            const char* wl = (const char*)(g_wl + (size_t)(bn + r)*HIDDEN + k0) + cb;
            cpa16(base + so,           xh);
            cpa16(base + GTILE + so,   xl);
            cpa16(base + 2*GTILE + so, wh);
            cpa16(base + 3*GTILE + so, wl);
        }
    };

    load_stage(0, 0); CP_COMMIT();

    for (int c = 0; c < 16; c++) {
        int s = c & 1;
        if (c < 15) { load_stage(s ^ 1, c + 1); CP_COMMIT(); CP_WAIT(1); }
        else        { CP_WAIT(0); }
        __syncthreads();

        uint32_t tb = sb + s * GSTAGE;
        int arow = wm + (lane & 15);
        int bro  = wn + ((lane >> 4) & 1)*8 + (lane & 7);
        #pragma unroll
        for (int ks = 0; ks < 4; ks++) {
            int acb = ks*32 + ((lane >> 4) & 1)*16;
            int bcb = ks*32 + ((lane >> 3) & 1)*16;
            uint32_t ah[4][4], al[4][4];
            #pragma unroll
            for (int mt = 0; mt < 4; mt++) {
                uint32_t so = SWZ((arow + mt*16)*128 + acb);
                ldsm4(ah[mt], tb + so);
                ldsm4(al[mt], tb + GTILE + so);
            }
            #pragma unroll
            for (int nt2 = 0; nt2 < 2; nt2++) {
                uint32_t so = SWZ((bro + nt2*16)*128 + bcb);
                uint32_t bh4[4], bl4[4];
                ldsm4(bh4, tb + 2*GTILE + so);
                ldsm4(bl4, tb + 3*GTILE + so);
                #pragma unroll
                for (int mt = 0; mt < 4; mt++) {
                    mma16816(acc[mt][nt2*2],   ah[mt], bh4[0], bh4[1]);
                    mma16816(acc[mt][nt2*2+1], ah[mt], bh4[2], bh4[3]);
                    mma16816(acc[mt][nt2*2],   al[mt], bh4[0], bh4[1]);
                    mma16816(acc[mt][nt2*2+1], al[mt], bh4[2], bh4[3]);
                    mma16816(acc[mt][nt2*2],   ah[mt], bl4[0], bl4[1]);
                    mma16816(acc[mt][nt2*2+1], ah[mt], bl4[2], bl4[3]);
                }
            }
        }
        __syncthreads();
    }

    // stage C to smem f32 [128][132]
    float* st = (float*)smg;
    int r0 = lane >> 2, col0 = (lane & 3)*2;
    #pragma unroll
    for (int mt = 0; mt < 4; mt++)
        #pragma unroll
        for (int nt = 0; nt < 4; nt++) {
            int rr = wm + mt*16 + r0;
            int cc = wn + nt*8 + col0;
            *(float2*)&st[(size_t)rr*132 + cc]       = make_float2(acc[mt][nt][0], acc[mt][nt][1]);
            *(float2*)&st[(size_t)(rr + 8)*132 + cc] = make_float2(acc[mt][nt][2], acc[mt][nt][3]);
        }
    __syncthreads();

    int p    = bn >> 10;
    int coff = bn & 1023;
    const float* bias = (p == 0) ? bq : ((p == 1) ? bk : bv);
    float scale = (p == 0) ? 0.125f : 1.0f;
    __nv_bfloat16* dh = (p == 0) ? gQh : ((p == 1) ? gKh : gVh);
    __nv_bfloat16* dl = (p == 0) ? gQl : ((p == 1) ? gKl : gVl);

    // FIXED: 128 rows x 32 float4-chunks (was >>4 / &15 -> OOB)
    #pragma unroll
    for (int it = 0; it < 16; it++) {
        int idx = tid + it*256;
        int r = idx >> 5, c4 = (idx & 31)*4;
        float4 v = *(float4*)&st[(size_t)r*132 + c4];
        int colg = coff + c4;
        float4 bi = *(const float4*)&bias[colg];
        v.x = (v.x + bi.x)*scale; v.y = (v.y + bi.y)*scale;
        v.z = (v.z + bi.z)*scale; v.w = (v.w + bi.w)*scale;
        uint32_t h01 = pkbf(v.x, v.y), h23 = pkbf(v.z, v.w);
        uint32_t l01 = pkbf(v.x - bflo(h01), v.y - bfhi(h01));
        uint32_t l23 = pkbf(v.z - bflo(h23), v.w - bfhi(h23));
        int m  = bm + r;
        int bb = m >> 11, sq = m & 2047;
        int h  = colg >> 6, d = colg & 63;
        size_t o = ((size_t)(bb*HEADS + h)*SEQ + sq)*HDIM + d;
        *(uint2*)&dh[o] = make_uint2(h01, h23);
        *(uint2*)&dl[o] = make_uint2(l01, l23);
    }
}

// ---------------------------------------------------------------------------
// Kernel 3: flash attention on mma.sync bf16 split.
// ---------------------------------------------------------------------------
#define ATILE 8192                   /* 64x64 bf16 tile */
#define AT_Q   8192                  /* after 8KB mask */
#define AT_KV  24576
#define AT_STG (4*ATILE)
#define AT_SMEM (AT_KV + 2*AT_STG)   /* 90112 */

__global__ __launch_bounds__(128) void attn_mma(
        const float* __restrict__ mask,
        float* __restrict__ out) {
    extern __shared__ char sma[];
    uint32_t sb = smem_u32(sma);
    int tid = threadIdx.x, lane = tid & 31, wid = tid >> 5;
    int bh = blockIdx.y;
    int b = bh >> 4, h = bh & 15;
    int q0 = blockIdx.x * 64;

    // mask row -> smem
    float* Ms = (float*)sma;
    #pragma unroll
    for (int it = 0; it < 4; it++) {
        int i4 = (tid + it*128)*4;
        *(float4*)&Ms[i4] = *(const float4*)&mask[(size_t)b*SEQ + i4];
    }
    // Q tiles -> smem
    {
        const char* qh = (const char*)(gQh + ((size_t)bh*SEQ + q0)*HDIM);
        const char* ql = (const char*)(gQl + ((size_t)bh*SEQ + q0)*HDIM);
        #pragma unroll
        for (int it = 0; it < 4; it++) {
            int idx = tid + it*128;
            int r = idx >> 3, cb = (idx & 7) << 4;
            uint32_t so = SWZ(r*128 + cb);
            *(uint4*)(sma + AT_Q + so)         = *(const uint4*)(qh + r*128 + cb);
            *(uint4*)(sma + AT_Q + ATILE + so) = *(const uint4*)(ql + r*128 + cb);
        }
    }

    auto load_kv = [&](int s, int c) {
        size_t roff = ((size_t)bh*SEQ + c*64)*HDIM;
        uint32_t base = sb + AT_KV + s*AT_STG;
        const char* kh = (const char*)(gKh + roff);
        const char* kl = (const char*)(gKl + roff);
        const char* vh = (const char*)(gVh + roff);
        const char* vl = (const char*)(gVl + roff);
        #pragma unroll
        for (int it = 0; it < 4; it++) {
            int idx = tid + it*128;
            int r = idx >> 3, cb = (idx & 7) << 4;
            uint32_t so = SWZ(r*128 + cb);
            cpa16(base + so,           kh + r*128 + cb);
            cpa16(base + ATILE + so,   kl + r*128 + cb);
            cpa16(base + 2*ATILE + so, vh + r*128 + cb);
            cpa16(base + 3*ATILE + so, vl + r*128 + cb);
        }
    };

    load_kv(0, 0); CP_COMMIT();
    __syncthreads();

    uint32_t qfh[4][4], qfl[4][4];
    {
        int arow = wid*16 + (lane & 15);
        #pragma unroll
        for (int ks = 0; ks < 4; ks++) {
            int acb = ks*32 + ((lane >> 4) & 1)*16;
            uint32_t so = SWZ(arow*128 + acb);
            ldsm4(qfh[ks], sb + AT_Q + so);
            ldsm4(qfl[ks], sb + AT_Q + ATILE + so);
        }
    }

    float o[8][4];
    #pragma unroll
    for (int i = 0; i < 8; i++)
        #pragma unroll
        for (int j = 0; j < 4; j++) o[i][j] = 0.0f;
    float m0 = -1e30f, m1 = -1e30f, l0 = 0.0f, l1 = 0.0f;

    for (int c = 0; c < 32; c++) {
        int s = c & 1;
        if (c < 31) { load_kv(s ^ 1, c + 1); CP_COMMIT(); CP_WAIT(1); }
        else        { CP_WAIT(0); }
        __syncthreads();

        uint32_t kb = sb + AT_KV + s*AT_STG;

        float sc[8][4];
        #pragma unroll
        for (int i = 0; i < 8; i++)
            #pragma unroll
            for (int j = 0; j < 4; j++) sc[i][j] = 0.0f;

        int bro = (lane & 7) + ((lane >> 4) & 1)*8;
        #pragma unroll
        for (int ks = 0; ks < 4; ks++) {
            int bcb = ks*32 + ((lane >> 3) & 1)*16;
            #pragma unroll
            for (int nt2 = 0; nt2 < 4; nt2++) {
                uint32_t so = SWZ((nt2*16 + bro)*128 + bcb);
                uint32_t kh4[4], kl4[4];
                ldsm4(kh4, kb + so);
                ldsm4(kl4, kb + ATILE + so);
                mma16816(sc[nt2*2],   qfh[ks], kh4[0], kh4[1]);
                mma16816(sc[nt2*2+1], qfh[ks], kh4[2], kh4[3]);
                mma16816(sc[nt2*2],   qfl[ks], kh4[0], kh4[1]);
                mma16816(sc[nt2*2+1], qfl[ks], kh4[2], kh4[3]);
                mma16816(sc[nt2*2],   qfh[ks], kl4[0], kl4[1]);
                mma16816(sc[nt2*2+1], qfh[ks], kl4[2], kl4[3]);
            }
        }

        int ckv = c*64;
        int col0 = (lane & 3)*2;
        #pragma unroll
        for (int nt = 0; nt < 8; nt++) {
            float2 mk = *(float2*)&Ms[ckv + nt*8 + col0];
            sc[nt][0] += mk.x; sc[nt][1] += mk.y;
            sc[nt][2] += mk.x; sc[nt][3] += mk.y;
        }
        float mx0 = sc[0][0], mx1 = sc[0][2];
        #pragma unroll
        for (int nt = 0; nt < 8; nt++) {
            mx0 = fmaxf(mx0, fmaxf(sc[nt][0], sc[nt][1]));
            mx1 = fmaxf(mx1, fmaxf(sc[nt][2], sc[nt][3]));
        }
        mx0 = fmaxf(mx0, __shfl_xor_sync(~0u, mx0, 1));
        mx0 = fmaxf(mx0, __shfl_xor_sync(~0u, mx0, 2));
        mx1 = fmaxf(mx1, __shfl_xor_sync(~0u, mx1, 1));
        mx1 = fmaxf(mx1, __shfl_xor_sync(~0u, mx1, 2));
        float mn0 = fmaxf(m0, mx0), mn1 = fmaxf(m1, mx1);
        float cr0 = __expf(m0 - mn0), cr1 = __expf(m1 - mn1);
        m0 = mn0; m1 = mn1;
        float s0 = 0.0f, s1 = 0.0f;
        #pragma unroll
        for (int nt = 0; nt < 8; nt++) {
            sc[nt][0] = __expf(sc[nt][0] - m0);
            sc[nt][1] = __expf(sc[nt][1] - m0);
            sc[nt][2] = __expf(sc[nt][2] - m1);
            sc[nt][3] = __expf(sc[nt][3] - m1);
            s0 += sc[nt][0] + sc[nt][1];
            s1 += sc[nt][2] + sc[nt][3];
        }
        s0 += __shfl_xor_sync(~0u, s0, 1); s0 += __shfl_xor_sync(~0u, s0, 2);
        s1 += __shfl_xor_sync(~0u, s1, 1); s1 += __shfl_xor_sync(~0u, s1, 2);
        l0 = l0*cr0 + s0;
        l1 = l1*cr1 + s1;
        #pragma unroll
        for (int nt = 0; nt < 8; nt++) {
            o[nt][0] *= cr0; o[nt][1] *= cr0;
            o[nt][2] *= cr1; o[nt][3] *= cr1;
        }

        uint32_t ph[4][4], pl[4][4];
        #pragma unroll
        for (int kt = 0; kt < 4; kt++) {
            float* e = sc[2*kt];
            float* f = sc[2*kt+1];
            ph[kt][0] = pkbf(e[0], e[1]);
            ph[kt][1] = pkbf(e[2], e[3]);
            ph[kt][2] = pkbf(f[0], f[1]);
            ph[kt][3] = pkbf(f[2], f[3]);
            pl[kt][0] = pkbf(e[0] - bflo(ph[kt][0]), e[1] - bfhi(ph[kt][0]));
            pl[kt][1] = pkbf(e[2] - bflo(ph[kt][1]), e[3] - bfhi(ph[kt][1]));
            pl[kt][2] = pkbf(f[0] - bflo(ph[kt][2]), f[1] - bfhi(ph[kt][2]));
            pl[kt][3] = pkbf(f[2] - bflo(ph[kt][3]), f[3] - bfhi(ph[kt][3]));
        }

        #pragma unroll
        for (int kt = 0; kt < 4; kt++) {
            int vrow = kt*16 + (lane & 15);
            #pragma unroll
            for (int dt2 = 0; dt2 < 4; dt2++) {
                int vcb = dt2*32 + ((lane >> 4) & 1)*16;
                uint32_t so = SWZ(vrow*128 + vcb);
                uint32_t vh4[4], vl4[4];
                ldsm4t(vh4, kb + 2*ATILE + so);
                ldsm4t(vl4, kb + 3*ATILE + so);
                mma16816(o[dt2*2],   ph[kt], vh4[0], vh4[1]);
                mma16816(o[dt2*2+1], ph[kt], vh4[2], vh4[3]);
                mma16816(o[dt2*2],   pl[kt], vh4[0], vh4[1]);
                mma16816(o[dt2*2+1], pl[kt], vh4[2], vh4[3]);
                mma16816(o[dt2*2],   ph[kt], vl4[0], vl4[1]);
                mma16816(o[dt2*2+1], ph[kt], vl4[2], vl4[3]);
            }
        }
        __syncthreads();
    }

    float inv0 = 1.0f / l0, inv1 = 1.0f / l1;
    float* Ost = (float*)(sma + AT_KV);
    int r0 = wid*16 + (lane >> 2), col0 = (lane & 3)*2;
    #pragma unroll
    for (int nt = 0; nt < 8; nt++) {
        *(float2*)&Ost[(size_t)r0*68 + nt*8 + col0] =
            make_float2(o[nt][0]*inv0, o[nt][1]*inv0);
        *(float2*)&Ost[(size_t)(r0 + 8)*68 + nt*8 + col0] =
            make_float2(o[nt][2]*inv1, o[nt][3]*inv1);
    }
    __syncthreads();
    #pragma unroll
    for (int it = 0; it < 8; it++) {
        int idx = tid + it*128;
        int r = idx >> 4, c4 = (idx & 15)*4;
        float4 v = *(float4*)&Ost[(size_t)r*68 + c4];
        *(float4*)&out[((size_t)b*SEQ + q0 + r)*HIDDEN + h*HDIM + c4] = v;
    }
}

// ---------------------------------------------------------------------------
extern "C" void kernel_launch(void* const* d_in, const int* in_sizes, int n_in,
                              void* d_out, int out_size) {
    const float* hs   = (const float*)d_in[0];
    const float* mask = (const float*)d_in[1];
    const float* Wq = (const float*)d_in[2];
    const float* bq = (const float*)d_in[3];
    const float* Aq = (const float*)d_in[4];
    const float* Bq = (const float*)d_in[5];
    const float* Wk = (const float*)d_in[6];
    const float* bk = (const float*)d_in[7];
    const float* Ak = (const float*)d_in[8];
    const float* Bk = (const float*)d_in[9];
    const float* Wv = (const float*)d_in[10];
    const float* bv = (const float*)d_in[11];
    const float* Av = (const float*)d_in[12];
    const float* Bv = (const float*)d_in[13];
    float* out = (float*)d_out;

    static int attr_set = 0;
    if (!attr_set) {
        cudaFuncSetAttribute(qkv_gemm_mma,
            cudaFuncAttributeMaxDynamicSharedMemorySize, GEMM_SMEM);
        cudaFuncSetAttribute(attn_mma,
            cudaFuncAttributeMaxDynamicSharedMemorySize, AT_SMEM);
        attr_set = 1;
    }

    // 1. Split inputs to bf16 hi/lo (+ fold LoRA into Weff)
    xsplit_kernel<<<NTOK*HIDDEN/1024, 256>>>(hs);
    wsplit_kernel<<<HIDDEN, 256>>>(Wq, Aq, Bq, 0);
    wsplit_kernel<<<HIDDEN, 256>>>(Wk, Ak, Bk, 1);
    wsplit_kernel<<<HIDDEN, 256>>>(Wv, Av, Bv, 2);

    // 2. QKV GEMM (tensor cores)
    {
        dim3 grid(3*HIDDEN/128, NTOK/128);
        qkv_gemm_mma<<<grid, 256, GEMM_SMEM>>>(bq, bk, bv);
    }

    // 3. Flash attention (tensor cores)
    {
        dim3 grid(SEQ/64, NBH);
        attn_mma<<<grid, 128, AT_SMEM>>>(mask, out);
    }
}